// round 1
// baseline (speedup 1.0000x reference)
#include <cuda_runtime.h>

// Problem constants
#define TOK_TOTAL 4096      // B_SZ * L = 2 * 2048
#define Dm        1024
#define Nn        16
#define TPB       256
#define TOKS      8                       // tokens per block
#define NBLK      (TOK_TOTAL / TOKS)      // 512 blocks
#define OUT_F4_PER_TOK 8196               // (2*1024+1)*16/4 floats per token in float4s

// Shared memory layout (float4 units)
#define SM_F4_A   0                       // A: 16384 floats = 4096 f4 (64 KB)
#define SM_F4_X   4096                    // x: 8 tokens * 1024 floats = 2048 f4 (32 KB)
#define SM_F4_D   6144                    // Delta: 1024 floats = 256 f4 (4 KB)
#define SM_F4_END 6400
#define SM_PROJ_F (SM_F4_END * 4)         // float offset 25600: proj[8][34]
#define SM_TOTAL_F (SM_PROJ_F + 8 * 34)   // 25872 floats = 103488 bytes

__device__ __forceinline__ float softplus_f(float v) {
    // matches jax.nn.softplus = max(x,0) + log1p(exp(-|x|))
    return fmaxf(v, 0.0f) + log1pf(__expf(-fabsf(v)));
}

__global__ void __launch_bounds__(TPB, 2) ssm_expand_kernel(
    const float* __restrict__ x,
    const float* __restrict__ Wb,
    const float* __restrict__ Wc,
    const float* __restrict__ Wd,
    const float* __restrict__ A,
    const float* __restrict__ dp,
    float* __restrict__ out)
{
    extern __shared__ float4 sm4[];
    float*  smf  = (float*)sm4;
    float4* sA   = sm4 + SM_F4_A;
    float4* sx   = sm4 + SM_F4_X;
    float4* sD4  = sm4 + SM_F4_D;
    float*  sDs  = (float*)sD4;
    float*  sxf  = (float*)sx;
    float*  proj = smf + SM_PROJ_F;       // [8][34]: B(0..15) C(16..31) s_delta(32)

    const int tid  = threadIdx.x;
    const int bt   = blockIdx.x;          // token-group index
    const int lane = tid & 31;
    const int w    = tid >> 5;

    // ---- Stage A[1024][16] into shared (64 KB), reused by all 8 tokens ----
    const float4* A4 = (const float4*)A;
    #pragma unroll
    for (int i = 0; i < 4096 / TPB; ++i)        // 16 iters
        sA[tid + i * TPB] = __ldg(A4 + tid + i * TPB);

    // ---- Stage 8 contiguous x rows (32 KB) ----
    const float4* x4 = (const float4*)x + (size_t)bt * (TOKS * Dm / 4);
    #pragma unroll
    for (int i = 0; i < (TOKS * Dm / 4) / TPB; ++i)  // 8 iters
        sx[tid + i * TPB] = __ldg(x4 + tid + i * TPB);

    __syncthreads();

    // ---- Projections: 33 dot products x 8 tokens. Warp w owns cols {w, w+8, ...} ----
    // Weight float4 loaded ONCE per block and FMA'd against all 8 tokens.
    for (int c = w; c < 33; c += 8) {
        const float* Wrow = (c < 16) ? (Wb + c * Dm)
                          : (c < 32) ? (Wc + (c - 16) * Dm)
                          : Wd;
        const float4* W4 = (const float4*)Wrow;
        float acc[TOKS];
        #pragma unroll
        for (int t = 0; t < TOKS; ++t) acc[t] = 0.0f;
        #pragma unroll
        for (int k = 0; k < 8; ++k) {
            float4 wv = __ldg(W4 + lane + 32 * k);
            #pragma unroll
            for (int t = 0; t < TOKS; ++t) {
                float4 xv = sx[t * 256 + lane + 32 * k];
                acc[t] = fmaf(xv.x, wv.x, acc[t]);
                acc[t] = fmaf(xv.y, wv.y, acc[t]);
                acc[t] = fmaf(xv.z, wv.z, acc[t]);
                acc[t] = fmaf(xv.w, wv.w, acc[t]);
            }
        }
        #pragma unroll
        for (int t = 0; t < TOKS; ++t) {
            float a = acc[t];
            a += __shfl_xor_sync(0xffffffffu, a, 16);
            a += __shfl_xor_sync(0xffffffffu, a, 8);
            a += __shfl_xor_sync(0xffffffffu, a, 4);
            a += __shfl_xor_sync(0xffffffffu, a, 2);
            a += __shfl_xor_sync(0xffffffffu, a, 1);
            if (lane == 0) proj[t * 34 + c] = a;
        }
    }

    // Each thread owns d = 4*tid .. 4*tid+3 for the softplus stage
    const float4* dp4 = (const float4*)dp;
    float4 dpv = __ldg(dp4 + tid);

    float4* out4 = (float4*)out;

    // ---- Per-token expansion ----
    for (int tt = 0; tt < TOKS; ++tt) {
        __syncthreads();   // (a) proj ready on first iter; (b) prev iter done reading sDs

        const float sdel = proj[tt * 34 + 32];
        float4 sp;
        sp.x = softplus_f(sdel + dpv.x);
        sp.y = softplus_f(sdel + dpv.y);
        sp.z = softplus_f(sdel + dpv.z);
        sp.w = softplus_f(sdel + dpv.w);
        sD4[tid] = sp;     // Delta[1024] for this token
        __syncthreads();

        const int token = bt * TOKS + tt;
        float4* ob = out4 + (size_t)token * OUT_F4_PER_TOK;
        const float* projB = proj + tt * 34;

        // 4096 float4s of A_bar + 4096 float4s of deltaB_x, fully coalesced.
        // f = thread's float4 index into the [1024][16] plane: d = f>>2, n0 = (f&3)*4
        #pragma unroll 8
        for (int j = 0; j < 16; ++j) {
            const int f  = tid + j * TPB;
            const int d  = f >> 2;
            const int n0 = (f & 3) * 4;
            const float Delta = sDs[d];
            const float xd    = sxf[tt * Dm + d];
            const float4 a    = sA[f];

            float4 ab;
            ab.x = __expf(Delta * a.x);
            ab.y = __expf(Delta * a.y);
            ab.z = __expf(Delta * a.z);
            ab.w = __expf(Delta * a.w);

            // deltaB_x = (A_bar - 1)/dA * Delta * B[n] * x[d] = (A_bar - 1) * B[n] * x[d] / A
            float4 o2;
            o2.x = __fdividef((ab.x - 1.0f) * (projB[n0 + 0] * xd), a.x);
            o2.y = __fdividef((ab.y - 1.0f) * (projB[n0 + 1] * xd), a.y);
            o2.z = __fdividef((ab.z - 1.0f) * (projB[n0 + 2] * xd), a.z);
            o2.w = __fdividef((ab.w - 1.0f) * (projB[n0 + 3] * xd), a.w);

            __stcs(ob + f, ab);              // A_bar plane  [0, 4096)
            __stcs(ob + 4096 + f, o2);       // deltaB_x     [4096, 8192)
        }

        // C row: 16 floats at plane offset 8192 f4
        if (tid < 4) {
            const float* pc = proj + tt * 34 + 16 + tid * 4;
            float4 cv = make_float4(pc[0], pc[1], pc[2], pc[3]);
            __stcs(ob + 8192 + tid, cv);
        }
    }
}

extern "C" void kernel_launch(void* const* d_in, const int* in_sizes, int n_in,
                              void* d_out, int out_size)
{
    const float* x  = (const float*)d_in[0];
    const float* Wb = (const float*)d_in[1];
    const float* Wc = (const float*)d_in[2];
    const float* Wd = (const float*)d_in[3];
    const float* A  = (const float*)d_in[4];
    const float* dp = (const float*)d_in[5];

    const size_t smem = SM_TOTAL_F * sizeof(float);   // 103488 B -> needs opt-in
    cudaFuncSetAttribute(ssm_expand_kernel,
                         cudaFuncAttributeMaxDynamicSharedMemorySize, (int)smem);

    ssm_expand_kernel<<<NBLK, TPB, smem>>>(x, Wb, Wc, Wd, A, dp, (float*)d_out);
}